// round 1
// baseline (speedup 1.0000x reference)
#include <cuda_runtime.h>
#include <cuda_bf16.h>
#include <cstdint>

// Problem constants
#define BHALF 4096          // B
#define NROWS 8192          // 2B
#define DDIM  1024          // D
#define INVT  10.0f         // 1/temperature
// exp(sim) = 2^(sim*log2e); sim = dot*INVT -> y = dot * (INVT*log2e)
#define Y_SCALE 14.4269504088896341f

// GEMM tiling
#define MT 128              // rows per CTA
#define NT 128              // cols per column tile
#define KC 64               // K chunk per pipeline stage
#define ROW_BYTES 144       // 64 bf16 = 128B data + 16B pad (bank-conflict-free)
#define A_BYTES (128 * ROW_BYTES)     // 18432
#define STAGE_BYTES (2 * A_BYTES)     // 36864 (A + B)
#define NSTAGES 3
#define SMEM_TOTAL (NSTAGES * STAGE_BYTES)  // 110592
#define NSPLITS 4           // column splits across blockIdx.y

// Device-global scratch (allocation-free rule: __device__ arrays)
__device__ __nv_bfloat16 g_fn[NROWS * DDIM];   // normalized bf16 matrix (16 MB)
__device__ float g_rowsum[NROWS];
__device__ float g_pos[NROWS];

// ---------------------------------------------------------------------------
// fast exp2: 2^y with |y| <= ~15, rel err ~2.4e-6 (degree-5 poly on [-.5,.5])
// ---------------------------------------------------------------------------
__device__ __forceinline__ float fexp2f(float y) {
    float t = y + 12582912.0f;               // round-to-nearest int via magic
    int   i = __float_as_int(t);
    float nf = t - 12582912.0f;
    float f  = y - nf;                       // f in [-0.5, 0.5]
    float p  = 1.33335581e-3f;
    p = fmaf(p, f, 9.61812910e-3f);
    p = fmaf(p, f, 5.55041086e-2f);
    p = fmaf(p, f, 2.40226507e-1f);
    p = fmaf(p, f, 6.93147182e-1f);
    p = fmaf(p, f, 1.0f);
    // (n + 127) << 23 ; n = i - 0x4B400000
    float s = __int_as_float((i + (127 - 0x4B400000)) << 23);
    return p * s;
}

// ---------------------------------------------------------------------------
// Kernel 1: row L2-normalize (fp32 norm) -> bf16 matrix; zero accumulators
// ---------------------------------------------------------------------------
__global__ void __launch_bounds__(256) norm_kernel(const float* __restrict__ v1,
                                                   const float* __restrict__ v2) {
    int row = blockIdx.x;
    const float* src = (row < BHALF) ? (v1 + (size_t)row * DDIM)
                                     : (v2 + (size_t)(row - BHALF) * DDIM);
    float4 v = reinterpret_cast<const float4*>(src)[threadIdx.x];
    float ss = v.x * v.x + v.y * v.y + v.z * v.z + v.w * v.w;
    #pragma unroll
    for (int o = 16; o; o >>= 1) ss += __shfl_xor_sync(0xFFFFFFFFu, ss, o);
    __shared__ float wred[8];
    if ((threadIdx.x & 31) == 0) wred[threadIdx.x >> 5] = ss;
    __syncthreads();
    float tot = wred[0] + wred[1] + wred[2] + wred[3]
              + wred[4] + wred[5] + wred[6] + wred[7];
    float scale = 1.0f / fmaxf(sqrtf(tot), 1e-12f);

    __nv_bfloat162* dst = reinterpret_cast<__nv_bfloat162*>(g_fn + (size_t)row * DDIM);
    __nv_bfloat162 h0, h1;
    h0.x = __float2bfloat16(v.x * scale); h0.y = __float2bfloat16(v.y * scale);
    h1.x = __float2bfloat16(v.z * scale); h1.y = __float2bfloat16(v.w * scale);
    dst[threadIdx.x * 2 + 0] = h0;
    dst[threadIdx.x * 2 + 1] = h1;

    if (threadIdx.x == 0) { g_rowsum[row] = 0.0f; g_pos[row] = 0.0f; }
}

// ---------------------------------------------------------------------------
// PTX helpers
// ---------------------------------------------------------------------------
__device__ __forceinline__ void cp_async16(unsigned dst, const void* src) {
    asm volatile("cp.async.cg.shared.global [%0], [%1], 16;\n"
                 :: "r"(dst), "l"(src) : "memory");
}
__device__ __forceinline__ void cp_commit() {
    asm volatile("cp.async.commit_group;\n" ::: "memory");
}
__device__ __forceinline__ void ldmatrix_x4(unsigned& r0, unsigned& r1,
                                            unsigned& r2, unsigned& r3, unsigned addr) {
    asm volatile("ldmatrix.sync.aligned.m8n8.x4.shared.b16 {%0,%1,%2,%3}, [%4];\n"
                 : "=r"(r0), "=r"(r1), "=r"(r2), "=r"(r3) : "r"(addr));
}
__device__ __forceinline__ void mma_bf16(float& d0, float& d1, float& d2, float& d3,
                                         unsigned a0, unsigned a1, unsigned a2, unsigned a3,
                                         unsigned b0, unsigned b1) {
    asm volatile("mma.sync.aligned.m16n8k16.row.col.f32.bf16.bf16.f32 "
                 "{%0,%1,%2,%3}, {%4,%5,%6,%7}, {%8,%9}, {%0,%1,%2,%3};\n"
                 : "+f"(d0), "+f"(d1), "+f"(d2), "+f"(d3)
                 : "r"(a0), "r"(a1), "r"(a2), "r"(a3), "r"(b0), "r"(b1));
}

// Copy one K-chunk (A tile 128xKC rows of rowblock, B tile 128xKC rows of colblock)
__device__ __forceinline__ void load_tiles(unsigned smem_base, int stage,
                                           int rowblock, int colblock, int kc, int tid) {
    unsigned base = smem_base + stage * STAGE_BYTES;
    const __nv_bfloat16* fn = g_fn;
    #pragma unroll
    for (int it = 0; it < 8; it++) {
        int c   = tid + it * 256;          // 0..2047
        int isB = c >> 10;                 // 0: A, 1: B
        int cl  = c & 1023;
        int r   = cl >> 3;                 // row within tile (0..127)
        int p   = cl & 7;                  // 16B chunk within row (0..7)
        int srow = (isB ? colblock : rowblock) * 128 + r;
        const void* src = fn + (size_t)srow * DDIM + kc * KC + p * 8;
        unsigned dst = base + isB * A_BYTES + r * ROW_BYTES + p * 16;
        cp_async16(dst, src);
    }
}

// ---------------------------------------------------------------------------
// Epilogue over one 128x128 accumulator tile.
// MODE 0: plain   MODE 1: diagonal tile (skip i==j)   MODE 2: positive tile
// ---------------------------------------------------------------------------
template <int MODE>
__device__ __forceinline__ void epilogue(const float (&acc)[16][4], int lane, int wid,
                                         float& rs_lo, float& rs_hi,
                                         float& pv_lo, float& pv_hi) {
    const int r_lo  = wid * 16 + (lane >> 2);     // local row of c0/c1
    const int cbase = (lane & 3) * 2;
    #pragma unroll
    for (int p = 0; p < 16; p++) {
        int c0 = p * 8 + cbase;
        #pragma unroll
        for (int e = 0; e < 4; e++) {
            float a   = acc[p][e];
            int   col = c0 + (e & 1);
            int   row = r_lo + ((e & 2) ? 8 : 0);
            float ev  = fexp2f(a * Y_SCALE);
            if (MODE == 1) { if (row == col) ev = 0.0f; }
            if (MODE == 2) {
                if (row == col) {
                    if (e < 2) pv_lo += a * INVT; else pv_hi += a * INVT;
                }
            }
            if (e < 2) rs_lo += ev; else rs_hi += ev;
        }
    }
}

// ---------------------------------------------------------------------------
// Kernel 2: fused sim GEMM + exp row-sum + pos extraction
// grid (64, NSPLITS), 256 threads (8 warps x 16 rows each)
// ---------------------------------------------------------------------------
__global__ void __launch_bounds__(256, 2) simexp_kernel() {
    extern __shared__ char smem[];
    unsigned smem_base = (unsigned)__cvta_generic_to_shared(smem);

    const int tid  = threadIdx.x;
    const int lane = tid & 31;
    const int wid  = tid >> 5;
    const int rowblock = blockIdx.x;
    const int ysplit   = blockIdx.y;
    const int posblock = (rowblock + 32) & 63;

    // ldmatrix lane addresses (stage-relative)
    const unsigned a_addr0 = smem_base + (wid * 16 + (lane & 15)) * ROW_BYTES
                           + (lane >> 4) * 16;
    const unsigned b_row   = (lane & 7) + ((lane >> 4) << 3);
    const unsigned b_addr0 = smem_base + A_BYTES + b_row * ROW_BYTES
                           + ((lane >> 3) & 1) * 16;

    float rs_lo = 0.f, rs_hi = 0.f, pv_lo = 0.f, pv_hi = 0.f;

    const int NCHUNK = DDIM / KC;   // 16

    for (int t = 0; t < 64 / NSPLITS; t++) {
        int j = ysplit * (64 / NSPLITS) + t;     // column block 0..63

        __syncthreads();   // protect stage reuse across column tiles
        load_tiles(smem_base, 0, rowblock, j, 0, tid); cp_commit();
        load_tiles(smem_base, 1, rowblock, j, 1, tid); cp_commit();

        float acc[16][4];
        #pragma unroll
        for (int p = 0; p < 16; p++)
            #pragma unroll
            for (int e = 0; e < 4; e++) acc[p][e] = 0.0f;

        for (int kc = 0; kc < NCHUNK; kc++) {
            if (kc < NCHUNK - 1) asm volatile("cp.async.wait_group 1;\n" ::: "memory");
            else                 asm volatile("cp.async.wait_group 0;\n" ::: "memory");
            __syncthreads();
            if (kc + 2 < NCHUNK) {
                load_tiles(smem_base, (kc + 2) % NSTAGES, rowblock, j, kc + 2, tid);
                cp_commit();
            }
            unsigned sA = a_addr0 + (kc % NSTAGES) * STAGE_BYTES;
            unsigned sB = b_addr0 + (kc % NSTAGES) * STAGE_BYTES;
            #pragma unroll
            for (int ks = 0; ks < 4; ks++) {              // 4 x k16 per chunk
                unsigned a0, a1, a2, a3;
                ldmatrix_x4(a0, a1, a2, a3, sA + ks * 32);
                #pragma unroll
                for (int p = 0; p < 8; p++) {             // 2 n-tiles per ldmatrix
                    unsigned b0, b1, b2, b3;
                    ldmatrix_x4(b0, b1, b2, b3, sB + p * (16 * ROW_BYTES) + ks * 32);
                    mma_bf16(acc[2*p][0],   acc[2*p][1],   acc[2*p][2],   acc[2*p][3],
                             a0, a1, a2, a3, b0, b1);
                    mma_bf16(acc[2*p+1][0], acc[2*p+1][1], acc[2*p+1][2], acc[2*p+1][3],
                             a0, a1, a2, a3, b2, b3);
                }
            }
        }

        if (j == rowblock)      epilogue<1>(acc, lane, wid, rs_lo, rs_hi, pv_lo, pv_hi);
        else if (j == posblock) epilogue<2>(acc, lane, wid, rs_lo, rs_hi, pv_lo, pv_hi);
        else                    epilogue<0>(acc, lane, wid, rs_lo, rs_hi, pv_lo, pv_hi);
    }

    // quad reduction (4 lanes share a row), then one atomicAdd per row
    rs_lo += __shfl_xor_sync(0xFFFFFFFFu, rs_lo, 1);
    rs_lo += __shfl_xor_sync(0xFFFFFFFFu, rs_lo, 2);
    rs_hi += __shfl_xor_sync(0xFFFFFFFFu, rs_hi, 1);
    rs_hi += __shfl_xor_sync(0xFFFFFFFFu, rs_hi, 2);
    pv_lo += __shfl_xor_sync(0xFFFFFFFFu, pv_lo, 1);
    pv_lo += __shfl_xor_sync(0xFFFFFFFFu, pv_lo, 2);
    pv_hi += __shfl_xor_sync(0xFFFFFFFFu, pv_hi, 1);
    pv_hi += __shfl_xor_sync(0xFFFFFFFFu, pv_hi, 2);
    if ((lane & 3) == 0) {
        int grow = rowblock * 128 + wid * 16 + (lane >> 2);
        atomicAdd(&g_rowsum[grow],     rs_lo);
        atomicAdd(&g_pos[grow],        pv_lo);
        atomicAdd(&g_rowsum[grow + 8], rs_hi);
        atomicAdd(&g_pos[grow + 8],    pv_hi);
    }
}

// ---------------------------------------------------------------------------
// Kernel 3: loss = mean(log(rowsum_i) - pos_i)
// ---------------------------------------------------------------------------
__global__ void __launch_bounds__(256) loss_kernel(float* __restrict__ out) {
    __shared__ double red[256];
    double s = 0.0;
    for (int i = threadIdx.x; i < NROWS; i += 256)
        s += (double)(logf(g_rowsum[i]) - g_pos[i]);
    red[threadIdx.x] = s;
    __syncthreads();
    for (int k = 128; k > 0; k >>= 1) {
        if (threadIdx.x < k) red[threadIdx.x] += red[threadIdx.x + k];
        __syncthreads();
    }
    if (threadIdx.x == 0) out[0] = (float)(red[0] / (double)NROWS);
}

// ---------------------------------------------------------------------------
extern "C" void kernel_launch(void* const* d_in, const int* in_sizes, int n_in,
                              void* d_out, int out_size) {
    const float* v1 = (const float*)d_in[0];
    const float* v2 = (const float*)d_in[1];
    float* out = (float*)d_out;

    cudaFuncSetAttribute(simexp_kernel,
                         cudaFuncAttributeMaxDynamicSharedMemorySize, SMEM_TOTAL);

    norm_kernel<<<NROWS, 256>>>(v1, v2);
    simexp_kernel<<<dim3(64, NSPLITS), 256, SMEM_TOTAL>>>();
    loss_kernel<<<1, 256>>>(out);
}

// round 3
// speedup vs baseline: 2.2748x; 2.2748x over previous
#include <cuda_runtime.h>
#include <cuda_bf16.h>
#include <cstdint>

// ---------------- problem constants ----------------
#define BHALF 4096
#define NROWS 8192
#define DDIM  1024
#define INVT  10.0f
#define Y_SCALE 14.4269504088896341f   // INVT * log2(e)

// ---------------- tiling ----------------
#define KC 64                 // K elems per pipeline stage
#define ROW_BYTES 144         // 64 bf16 = 128B + 16B pad
#define A_BYTES (128 * ROW_BYTES)          // 18432
#define STAGE_BYTES (2 * A_BYTES)          // 36864
#define NSTAGES 3
#define SMEM_TOTAL (NSTAGES * STAGE_BYTES) // 110592
#define NBLK 64               // 8192 / 128
#define NTILES (NBLK * (NBLK + 1) / 2)     // 2080 upper-triangle tiles

__device__ __align__(16) __nv_bfloat16 g_fn[NROWS * DDIM];  // normalized bf16 (16MB)
__device__ float g_rowsum[NROWS];
__device__ float g_pos[NROWS];

// ---------------------------------------------------------------------------
// fast 2^y, |y| <= ~15, rel err ~2e-6
// ---------------------------------------------------------------------------
__device__ __forceinline__ float fexp2f(float y) {
    float t = y + 12582912.0f;
    int   i = __float_as_int(t);
    float f = y - (t - 12582912.0f);
    float p = 1.33335581e-3f;
    p = fmaf(p, f, 9.61812910e-3f);
    p = fmaf(p, f, 5.55041086e-2f);
    p = fmaf(p, f, 2.40226507e-1f);
    p = fmaf(p, f, 6.93147182e-1f);
    p = fmaf(p, f, 1.0f);
    return p * __int_as_float((i + (127 - 0x4B400000)) << 23);
}

// ---------------------------------------------------------------------------
// Kernel 1: row L2-normalize -> bf16; zero accumulators
// ---------------------------------------------------------------------------
__global__ void __launch_bounds__(256) norm_kernel(const float* __restrict__ v1,
                                                   const float* __restrict__ v2) {
    int row = blockIdx.x;
    const float* src = (row < BHALF) ? (v1 + (size_t)row * DDIM)
                                     : (v2 + (size_t)(row - BHALF) * DDIM);
    float4 v = reinterpret_cast<const float4*>(src)[threadIdx.x];
    float ss = v.x*v.x + v.y*v.y + v.z*v.z + v.w*v.w;
    #pragma unroll
    for (int o = 16; o; o >>= 1) ss += __shfl_xor_sync(0xFFFFFFFFu, ss, o);
    __shared__ float wred[8];
    if ((threadIdx.x & 31) == 0) wred[threadIdx.x >> 5] = ss;
    __syncthreads();
    float tot = wred[0]+wred[1]+wred[2]+wred[3]+wred[4]+wred[5]+wred[6]+wred[7];
    float scale = 1.0f / fmaxf(sqrtf(tot), 1e-12f);
    __nv_bfloat162* dst = reinterpret_cast<__nv_bfloat162*>(g_fn + (size_t)row * DDIM);
    __nv_bfloat162 h0, h1;
    h0.x = __float2bfloat16(v.x*scale); h0.y = __float2bfloat16(v.y*scale);
    h1.x = __float2bfloat16(v.z*scale); h1.y = __float2bfloat16(v.w*scale);
    dst[threadIdx.x*2+0] = h0;
    dst[threadIdx.x*2+1] = h1;
    if (threadIdx.x == 0) { g_rowsum[row] = 0.0f; g_pos[row] = 0.0f; }
}

// ---------------------------------------------------------------------------
// PTX helpers
// ---------------------------------------------------------------------------
__device__ __forceinline__ void cp_async16(unsigned dst, const void* src) {
    asm volatile("cp.async.cg.shared.global [%0], [%1], 16;" :: "r"(dst), "l"(src) : "memory");
}
__device__ __forceinline__ void cp_commit() {
    asm volatile("cp.async.commit_group;" ::: "memory");
}
__device__ __forceinline__ void ldmatrix_x4(unsigned& r0, unsigned& r1,
                                            unsigned& r2, unsigned& r3, unsigned addr) {
    asm volatile("ldmatrix.sync.aligned.m8n8.x4.shared.b16 {%0,%1,%2,%3}, [%4];"
                 : "=r"(r0), "=r"(r1), "=r"(r2), "=r"(r3) : "r"(addr));
}
__device__ __forceinline__ void mma_bf16(float& d0, float& d1, float& d2, float& d3,
                                         unsigned a0, unsigned a1, unsigned a2, unsigned a3,
                                         unsigned b0, unsigned b1) {
    asm volatile("mma.sync.aligned.m16n8k16.row.col.f32.bf16.bf16.f32 "
                 "{%0,%1,%2,%3}, {%4,%5,%6,%7}, {%8,%9}, {%0,%1,%2,%3};"
                 : "+f"(d0), "+f"(d1), "+f"(d2), "+f"(d3)
                 : "r"(a0), "r"(a1), "r"(a2), "r"(a3), "r"(b0), "r"(b1));
}

// Load one K-chunk: A = rows of rb-block, B = rows of cb-block (both 128 x 64)
__device__ __forceinline__ void load_tiles(unsigned smem_base, int stage,
                                           int rb, int cb, int kc, int tid) {
    unsigned base = smem_base + stage * STAGE_BYTES;
    const __nv_bfloat16* fn = g_fn;
    #pragma unroll
    for (int it = 0; it < 8; it++) {
        int c   = tid + it * 256;          // 0..2047
        int isB = c >> 10;
        int cl  = c & 1023;
        int r   = cl >> 3;
        int p   = cl & 7;
        int srow = (isB ? cb : rb) * 128 + r;
        const void* src = fn + (size_t)srow * DDIM + kc * KC + p * 8;
        unsigned dst = base + isB * A_BYTES + r * ROW_BYTES + p * 16;
        cp_async16(dst, src);
    }
}

// ---------------------------------------------------------------------------
// Kernel 2: symmetric fused sim GEMM + exp row/col sums
// grid NTILES (one 128x128 upper-triangle tile per CTA), 256 threads
// warp grid: 4 (m) x 2 (n); warp tile 32 x 64
// ---------------------------------------------------------------------------
__global__ void __launch_bounds__(256, 2) simexp_kernel() {
    extern __shared__ char smem[];
    unsigned smem_base = (unsigned)__cvta_generic_to_shared(smem);

    const int tid  = threadIdx.x;
    const int lane = tid & 31;
    const int wid  = tid >> 5;
    const int wm   = wid & 3;          // warp row 0..3 (32 rows each)
    const int wn   = wid >> 2;         // warp col 0..1 (64 cols each)

    // decode upper-triangle tile index -> (rb, cb), cb >= rb
    const int t = blockIdx.x;
    int rb = (int)((129.0f - sqrtf(129.0f*129.0f - 8.0f*(float)t)) * 0.5f);
    if (rb > 63) rb = 63;
    if (rb < 0)  rb = 0;
    int off = rb*64 - rb*(rb-1)/2;
    while (off > t)                 { rb--; off = rb*64 - rb*(rb-1)/2; }
    while (off + (NBLK - rb) <= t)  { off += NBLK - rb; rb++; }
    const int cb = rb + (t - off);
    const bool is_diag = (cb == rb);
    const bool is_pos  = (cb == rb + 32);

    // ldmatrix lane base addresses (stage-relative)
    const unsigned a_base = smem_base + (wm*32 + (lane & 15)) * ROW_BYTES + (lane >> 4) * 16;
    const unsigned b_base = smem_base + A_BYTES
                          + (wn*64 + (lane & 7) + ((lane >> 4) << 3)) * ROW_BYTES
                          + ((lane >> 3) & 1) * 16;

    float acc[2][8][4];
    #pragma unroll
    for (int mf = 0; mf < 2; mf++)
        #pragma unroll
        for (int j = 0; j < 8; j++)
            #pragma unroll
            for (int e = 0; e < 4; e++) acc[mf][j][e] = 0.0f;

    const int NCHUNK = DDIM / KC;    // 16
    load_tiles(smem_base, 0, rb, cb, 0, tid); cp_commit();
    load_tiles(smem_base, 1, rb, cb, 1, tid); cp_commit();

    for (int kc = 0; kc < NCHUNK; kc++) {
        if (kc < NCHUNK - 1) asm volatile("cp.async.wait_group 1;" ::: "memory");
        else                 asm volatile("cp.async.wait_group 0;" ::: "memory");
        __syncthreads();
        if (kc + 2 < NCHUNK) {
            load_tiles(smem_base, (kc + 2) % NSTAGES, rb, cb, kc + 2, tid);
            cp_commit();
        }
        const unsigned sA = a_base + (kc % NSTAGES) * STAGE_BYTES;
        const unsigned sB = b_base + (kc % NSTAGES) * STAGE_BYTES;
        #pragma unroll
        for (int ks = 0; ks < 4; ks++) {
            unsigned a[2][4];
            #pragma unroll
            for (int mf = 0; mf < 2; mf++)
                ldmatrix_x4(a[mf][0], a[mf][1], a[mf][2], a[mf][3],
                            sA + mf * (16 * ROW_BYTES) + ks * 32);
            #pragma unroll
            for (int nf = 0; nf < 4; nf++) {
                unsigned b0, b1, b2, b3;
                ldmatrix_x4(b0, b1, b2, b3, sB + nf * (16 * ROW_BYTES) + ks * 32);
                #pragma unroll
                for (int mf = 0; mf < 2; mf++) {
                    mma_bf16(acc[mf][2*nf][0],   acc[mf][2*nf][1],
                             acc[mf][2*nf][2],   acc[mf][2*nf][3],
                             a[mf][0], a[mf][1], a[mf][2], a[mf][3], b0, b1);
                    mma_bf16(acc[mf][2*nf+1][0], acc[mf][2*nf+1][1],
                             acc[mf][2*nf+1][2], acc[mf][2*nf+1][3],
                             a[mf][0], a[mf][1], a[mf][2], a[mf][3], b2, b3);
                }
            }
        }
    }

    // ---------------- epilogue ----------------
    // rows:   r_local = wm*32 + mf*16 + (lane>>2) + (e&2 ? 8 : 0)
    // cols:   c_local = wn*64 + j*8 + (lane&3)*2 + (e&1)
    float rs[2][2] = {{0.f,0.f},{0.f,0.f}};   // [mf][lo/hi] row sums
    float cs[8][2];                            // [j][parity] col sums
    #pragma unroll
    for (int j = 0; j < 8; j++) { cs[j][0] = 0.f; cs[j][1] = 0.f; }

    const int rq = lane >> 2;      // 0..7
    const int cq = (lane & 3) * 2; // 0,2,4,6

    #pragma unroll
    for (int mf = 0; mf < 2; mf++) {
        #pragma unroll
        for (int j = 0; j < 8; j++) {
            #pragma unroll
            for (int e = 0; e < 4; e++) {
                float a  = acc[mf][j][e];
                int r_local = wm*32 + mf*16 + rq + ((e & 2) ? 8 : 0);
                int c_local = wn*64 + j*8 + cq + (e & 1);
                float ev = fexp2f(a * Y_SCALE);
                if (is_diag && r_local == c_local) ev = 0.0f;
                rs[mf][e >> 1] += ev;
                cs[j][e & 1]   += ev;
                if (is_pos && r_local == c_local) {
                    float pv = a * INVT;
                    atomicAdd(&g_pos[rb*128 + r_local], pv);
                    atomicAdd(&g_pos[cb*128 + c_local], pv);
                }
            }
        }
    }

    // row sums: reduce over lane&3 (cols), write rows of rb block
    #pragma unroll
    for (int mf = 0; mf < 2; mf++) {
        #pragma unroll
        for (int h = 0; h < 2; h++) {
            float v = rs[mf][h];
            v += __shfl_xor_sync(0xFFFFFFFFu, v, 1);
            v += __shfl_xor_sync(0xFFFFFFFFu, v, 2);
            if ((lane & 3) == 0)
                atomicAdd(&g_rowsum[rb*128 + wm*32 + mf*16 + rq + h*8], v);
        }
    }

    // col sums: reduce over lane>>2 (rows), write rows of cb block (symmetry)
    if (!is_diag) {
        #pragma unroll
        for (int j = 0; j < 8; j++) {
            #pragma unroll
            for (int par = 0; par < 2; par++) {
                float v = cs[j][par];
                v += __shfl_xor_sync(0xFFFFFFFFu, v, 4);
                v += __shfl_xor_sync(0xFFFFFFFFu, v, 8);
                v += __shfl_xor_sync(0xFFFFFFFFu, v, 16);
                if (lane < 4)
                    atomicAdd(&g_rowsum[cb*128 + wn*64 + j*8 + lane*2 + par], v);
            }
        }
    }
}

// ---------------------------------------------------------------------------
// Kernel 3: loss = mean(log(rowsum_i) - pos_i)
// ---------------------------------------------------------------------------
__global__ void __launch_bounds__(256) loss_kernel(float* __restrict__ out) {
    __shared__ double red[256];
    double s = 0.0;
    for (int i = threadIdx.x; i < NROWS; i += 256)
        s += (double)(logf(g_rowsum[i]) - g_pos[i]);
    red[threadIdx.x] = s;
    __syncthreads();
    for (int k = 128; k > 0; k >>= 1) {
        if (threadIdx.x < k) red[threadIdx.x] += red[threadIdx.x + k];
        __syncthreads();
    }
    if (threadIdx.x == 0) out[0] = (float)(red[0] / (double)NROWS);
}

// ---------------------------------------------------------------------------
extern "C" void kernel_launch(void* const* d_in, const int* in_sizes, int n_in,
                              void* d_out, int out_size) {
    const float* v1 = (const float*)d_in[0];
    const float* v2 = (const float*)d_in[1];
    float* out = (float*)d_out;

    cudaFuncSetAttribute(simexp_kernel,
                         cudaFuncAttributeMaxDynamicSharedMemorySize, SMEM_TOTAL);

    norm_kernel<<<NROWS, 256>>>(v1, v2);
    simexp_kernel<<<NTILES, 256, SMEM_TOTAL>>>();
    loss_kernel<<<1, 256>>>(out);
}